// round 1
// baseline (speedup 1.0000x reference)
#include <cuda_runtime.h>
#include <float.h>

#define BB 2
#define HH 12
#define NN 1600
#define DD 32
#define GG 48
#define KT 96
#define CC 384
#define BHc (BB*HH)          // 24
#define NQ (BHc*NN)          // 38400

// Scratch (no cudaMalloc allowed)
__device__ float g_qkv[3][BHc*NN*DD];      // [which][b*h][n][d]
__device__ int   g_gidx[NQ];
__device__ float g_qsum[BHc*GG*DD];
__device__ float g_gcnt[BHc*GG];
__device__ float g_qmean[BHc*GG*DD];
__device__ int   g_topk[BHc*GG*KT];
__device__ float g_att[BB*NN*HH*DD];       // [b][n][h][d]

__global__ void zero_kernel() {
    int i = blockIdx.x*blockDim.x + threadIdx.x;
    if (i < BHc*GG*DD) g_qsum[i] = 0.f;
    if (i < BHc*GG)    g_gcnt[i] = 0.f;
}

// out[m][col] = sum_k A[m][k] * B[col][k]   (NT GEMM, K=384, M=3200)
// MODE 0: A = x, scatter into g_qkv.  MODE 1: A = g_att, write d_out.
template<int MODE>
__global__ void gemm_nt(const float* __restrict__ A, const float* __restrict__ B,
                        float* __restrict__ out) {
    const int K = CC;
    __shared__ float As[16][128];
    __shared__ float Bs[16][128];
    const float* Ap = (MODE == 0) ? A : (const float*)g_att;
    int m0 = blockIdx.y * 128, n0 = blockIdx.x * 128;
    int tid = threadIdx.x;
    int tx = tid & 15, ty = tid >> 4;
    float acc[8][8] = {};
    for (int k0 = 0; k0 < K; k0 += 16) {
        #pragma unroll
        for (int s = 0; s < 2; s++) {
            int slot = tid + s * 256;
            int r = slot >> 2, c4 = (slot & 3) << 2;
            float4 va = *(const float4*)(Ap + (size_t)(m0 + r)*K + k0 + c4);
            As[c4+0][r] = va.x; As[c4+1][r] = va.y; As[c4+2][r] = va.z; As[c4+3][r] = va.w;
            float4 vb = *(const float4*)(B + (size_t)(n0 + r)*K + k0 + c4);
            Bs[c4+0][r] = vb.x; Bs[c4+1][r] = vb.y; Bs[c4+2][r] = vb.z; Bs[c4+3][r] = vb.w;
        }
        __syncthreads();
        #pragma unroll
        for (int kk = 0; kk < 16; kk++) {
            float a[8], b[8];
            *(float4*)&a[0] = *(const float4*)&As[kk][ty*8];
            *(float4*)&a[4] = *(const float4*)&As[kk][ty*8+4];
            *(float4*)&b[0] = *(const float4*)&Bs[kk][tx*8];
            *(float4*)&b[4] = *(const float4*)&Bs[kk][tx*8+4];
            #pragma unroll
            for (int i = 0; i < 8; i++)
                #pragma unroll
                for (int j = 0; j < 8; j++)
                    acc[i][j] += a[i] * b[j];
        }
        __syncthreads();
    }
    #pragma unroll
    for (int i = 0; i < 8; i++) {
        int m = m0 + ty*8 + i;
        int bi = m / NN, n = m % NN;
        #pragma unroll
        for (int j = 0; j < 8; j++) {
            int col = n0 + tx*8 + j;
            if (MODE == 0) {
                int which = col / (HH*DD);
                int r2 = col % (HH*DD);
                int head = r2 / DD, dd = r2 % DD;
                g_qkv[which][(((size_t)bi*HH + head)*NN + n)*DD + dd] = acc[i][j];
            } else {
                out[(size_t)m*(HH*DD) + col] = acc[i][j];
            }
        }
    }
}

// One warp per query: argmax over 48 group logits (first-max tie-break = jnp.argmax),
// accumulate group sums/counts.
__global__ void route_kernel(const float* __restrict__ w_gp) {
    int qid = blockIdx.x * 8 + (threadIdx.x >> 5);
    int lane = threadIdx.x & 31;
    int bh = qid / NN, n = qid % NN;
    int h = bh % HH;
    float ql = g_qkv[0][((size_t)bh*NN + n)*DD + lane];
    float best = -FLT_MAX; int bg = 0;
    for (int g = 0; g < GG; g++) {
        float v = ql * w_gp[(h*GG + g)*DD + lane];
        #pragma unroll
        for (int o = 16; o; o >>= 1) v += __shfl_xor_sync(0xffffffffu, v, o);
        if (v > best) { best = v; bg = g; }
    }
    if (lane == 0) {
        g_gidx[qid] = bg;
        atomicAdd(&g_gcnt[bh*GG + bg], 1.f);
    }
    atomicAdd(&g_qsum[(bh*GG + bg)*DD + lane], ql);
}

__global__ void qmean_kernel() {
    int i = blockIdx.x*blockDim.x + threadIdx.x;
    if (i < BHc*GG*DD)
        g_qmean[i] = g_qsum[i] / fmaxf(g_gcnt[i/DD], 1e-8f);
}

// One block per (b,h,g) row: qmw over 1600 keys, then iterative top-96
// (lowest-index tie-break matches lax.top_k stable order).
__global__ void qmw_topk_kernel() {
    int row = blockIdx.x;          // [0, BHc*GG)
    int bh = row / GG;
    __shared__ float qm[DD];
    __shared__ float vals[NN];
    __shared__ float rmax[8];
    __shared__ int   ridx[8];
    int tid = threadIdx.x;
    if (tid < DD) qm[tid] = g_qmean[row*DD + tid];
    __syncthreads();
    const float* kb = &g_qkv[1][(size_t)bh*NN*DD];
    for (int m = tid; m < NN; m += 256) {
        const float* kr = kb + (size_t)m*DD;
        float s = 0.f;
        #pragma unroll
        for (int dd = 0; dd < DD; dd++) s += qm[dd] * kr[dd];
        vals[m] = s;
    }
    __syncthreads();
    int lane = tid & 31, w = tid >> 5;
    for (int it = 0; it < KT; it++) {
        float bv = -FLT_MAX; int bi = 1 << 30;
        for (int m = tid; m < NN; m += 256) {
            float v = vals[m];
            if (v > bv) { bv = v; bi = m; }
        }
        #pragma unroll
        for (int o = 16; o; o >>= 1) {
            float ov = __shfl_xor_sync(0xffffffffu, bv, o);
            int   oi = __shfl_xor_sync(0xffffffffu, bi, o);
            if (ov > bv || (ov == bv && oi < bi)) { bv = ov; bi = oi; }
        }
        if (lane == 0) { rmax[w] = bv; ridx[w] = bi; }
        __syncthreads();
        if (tid == 0) {
            float fv = rmax[0]; int fi = ridx[0];
            #pragma unroll
            for (int ww = 1; ww < 8; ww++)
                if (rmax[ww] > fv || (rmax[ww] == fv && ridx[ww] < fi)) { fv = rmax[ww]; fi = ridx[ww]; }
            g_topk[row*KT + it] = fi;
            vals[fi] = -FLT_MAX;
        }
        __syncthreads();
    }
}

// One warp per query: softmax over its group's 96 keys, weighted sum of V.
__global__ void attn_kernel() {
    int qid = blockIdx.x * 8 + (threadIdx.x >> 5);
    int lane = threadIdx.x & 31;
    int bh = qid / NN, n = qid % NN;
    int bi = bh / HH, h = bh % HH;
    const float* kb = &g_qkv[1][(size_t)bh*NN*DD];
    const float* vb = &g_qkv[2][(size_t)bh*NN*DD];
    float ql = g_qkv[0][((size_t)bh*NN + n)*DD + lane];
    int g = g_gidx[qid];
    const int* tk = &g_topk[(bh*GG + g)*KT];

    float s[3]; int id[3];
    #pragma unroll
    for (int j = 0; j < KT; j++) {
        int idx = tk[j];
        float d = ql * kb[(size_t)idx*DD + lane];
        #pragma unroll
        for (int o = 16; o; o >>= 1) d += __shfl_xor_sync(0xffffffffu, d, o);
        if ((j & 31) == lane) { s[j >> 5] = d; id[j >> 5] = idx; }
    }
    const float scale = 0.17677669529663687f;  // 32^-0.5
    float mx = -FLT_MAX;
    #pragma unroll
    for (int t = 0; t < 3; t++) { s[t] *= scale; mx = fmaxf(mx, s[t]); }
    #pragma unroll
    for (int o = 16; o; o >>= 1) mx = fmaxf(mx, __shfl_xor_sync(0xffffffffu, mx, o));
    float psum = 0.f;
    #pragma unroll
    for (int t = 0; t < 3; t++) { s[t] = __expf(s[t] - mx); psum += s[t]; }
    #pragma unroll
    for (int o = 16; o; o >>= 1) psum += __shfl_xor_sync(0xffffffffu, psum, o);
    float acc = 0.f;
    #pragma unroll
    for (int j = 0; j < KT; j++) {
        float pj = __shfl_sync(0xffffffffu, s[j >> 5], j & 31);
        int  idx = __shfl_sync(0xffffffffu, id[j >> 5], j & 31);
        acc += pj * vb[(size_t)idx*DD + lane];
    }
    acc /= psum;
    g_att[(((size_t)bi*NN + n)*HH + h)*DD + lane] = acc;
}

extern "C" void kernel_launch(void* const* d_in, const int* in_sizes, int n_in,
                              void* d_out, int out_size) {
    const float* x      = (const float*)d_in[0];
    const float* w_qkv  = (const float*)d_in[1];
    const float* w_gp   = (const float*)d_in[2];
    const float* w_proj = (const float*)d_in[3];
    float* out = (float*)d_out;

    zero_kernel<<<149, 256>>>();
    gemm_nt<0><<<dim3(9, 25), 256>>>(x, w_qkv, nullptr);       // QKV: 3200x1152x384
    route_kernel<<<NQ/8, 256>>>(w_gp);
    qmean_kernel<<<144, 256>>>();
    qmw_topk_kernel<<<BHc*GG, 256>>>();
    attn_kernel<<<NQ/8, 256>>>();
    gemm_nt<1><<<dim3(3, 25), 256>>>(nullptr, w_proj, out);    // proj: 3200x384x384
}